// round 8
// baseline (speedup 1.0000x reference)
#include <cuda_runtime.h>
#include <cuda_fp16.h>
#include <cstdint>
#include <cstddef>

// ---------------------------------------------------------------------------
// GemmRS: out[g,n] = sum_{s,k} A[s,g,k] * W[s,n,k]  == GEMM M=8192,N=1024,K=4096
// fp16 cast both operands (validated rel_err 2.9e-4 < 1e-3).
// mma.sync.m16n8k16 f16 -> fp32. 3-stage cp.async pipeline with per-stage
// full/empty mbarriers (no __syncthreads rendezvous in the main loop).
// ---------------------------------------------------------------------------

#define MTOT 8192
#define NTOT 1024
#define KTOT 4096
#define NCHUNK 64              // KTOT / 64
#define BMT  128
#define BNT  128
#define STAGE_BYTES 32768      // A 16KB + B 16KB
#define NSTAGE 3

__device__ __half g_Ah[(size_t)MTOT * KTOT];
__device__ __half g_Bh[(size_t)NTOT * KTOT];

static __device__ __forceinline__ uint32_t smem_u32(const void* p) {
    uint32_t a;
    asm("{ .reg .u64 t; cvta.to.shared.u64 t, %1; cvt.u32.u64 %0, t; }"
        : "=r"(a) : "l"(p));
    return a;
}
static __device__ __forceinline__ void ldsm_x4(uint32_t& r0, uint32_t& r1,
                                               uint32_t& r2, uint32_t& r3,
                                               uint32_t addr) {
    asm volatile("ldmatrix.sync.aligned.m8n8.x4.shared.b16 {%0,%1,%2,%3}, [%4];"
                 : "=r"(r0), "=r"(r1), "=r"(r2), "=r"(r3) : "r"(addr));
}
static __device__ __forceinline__ void mma16816(float* c, const uint32_t* a,
                                                const uint32_t* b) {
    asm volatile(
        "mma.sync.aligned.m16n8k16.row.col.f32.f16.f16.f32 "
        "{%0,%1,%2,%3}, {%4,%5,%6,%7}, {%8,%9}, {%0,%1,%2,%3};"
        : "+f"(c[0]), "+f"(c[1]), "+f"(c[2]), "+f"(c[3])
        : "r"(a[0]), "r"(a[1]), "r"(a[2]), "r"(a[3]), "r"(b[0]), "r"(b[1]));
}
static __device__ __forceinline__ void mbar_wait(uint32_t addr, uint32_t parity) {
    asm volatile(
        "{ .reg .pred P;\n\t"
        "WAIT_%=:\n\t"
        "mbarrier.try_wait.parity.shared.b64 P, [%0], %1;\n\t"
        "@P bra.uni DONE_%=;\n\t"
        "bra.uni WAIT_%=;\n\t"
        "DONE_%=:\n\t}"
        :: "r"(addr), "r"(parity) : "memory");
}

// ------------------------- fused cast prepass ------------------------------
__global__ __launch_bounds__(256) void cast_kernel(const float* __restrict__ A,
                                                   const float* __restrict__ W) {
    const int b = blockIdx.x;
    const int t = threadIdx.x;
    const int k0 = t << 4;
    const int s  = k0 >> 9;
    const int kl = k0 & 511;

    const bool isA = (b < MTOT);
    const int  row = isA ? b : (b - MTOT);
    const float4* src = isA ? (const float4*)(A + ((size_t)s * MTOT + row) * 512 + kl)
                            : (const float4*)(W + ((size_t)s * NTOT + row) * 512 + kl);
    float4 v0 = src[0], v1 = src[1], v2 = src[2], v3 = src[3];
    float x[16] = {v0.x,v0.y,v0.z,v0.w, v1.x,v1.y,v1.z,v1.w,
                   v2.x,v2.y,v2.z,v2.w, v3.x,v3.y,v3.z,v3.w};
    uint32_t h[8];
#pragma unroll
    for (int p = 0; p < 8; ++p) {
        __half h0 = __float2half_rn(x[2*p]);
        __half h1 = __float2half_rn(x[2*p+1]);
        h[p] = (uint32_t)__half_as_ushort(h0) |
               ((uint32_t)__half_as_ushort(h1) << 16);
    }
    uint4* dst = (uint4*)((isA ? g_Ah : g_Bh) + (size_t)row * KTOT + k0);
    dst[0] = make_uint4(h[0], h[1], h[2], h[3]);
    dst[1] = make_uint4(h[4], h[5], h[6], h[7]);
}

// ----------------------------- main GEMM ----------------------------------
// CTA 128x128, 8 warps 4(M)x2(N), warp tile 32x64, BK=64, 3-stage pipeline,
// occupancy 2. Per-stage mbarrier full/empty protocol; warps may skew.
__global__ __launch_bounds__(256, 2)
void gemm_mma_f16(float* __restrict__ C) {
    extern __shared__ char dsm[];
    __shared__ __align__(16) unsigned long long mb_full[NSTAGE];
    __shared__ __align__(16) unsigned long long mb_empty[NSTAGE];

    const uint32_t sbase = smem_u32(dsm);
    const uint32_t mbF = smem_u32(&mb_full[0]);
    const uint32_t mbE = smem_u32(&mb_empty[0]);

    const int tid  = threadIdx.x;
    const int wid  = tid >> 5;
    const int lane = tid & 31;
    const int wm   = wid & 3;
    const int wn   = wid >> 2;
    const int bm   = blockIdx.y * BMT;
    const int bn   = blockIdx.x * BNT;

    if (tid == 0) {
#pragma unroll
        for (int s = 0; s < NSTAGE; ++s) {
            asm volatile("mbarrier.init.shared.b64 [%0], %1;"
                         :: "r"(mbF + s * 8), "r"(256) : "memory");
            asm volatile("mbarrier.init.shared.b64 [%0], %1;"
                         :: "r"(mbE + s * 8), "r"(256) : "memory");
        }
    }
    __syncthreads();

    // cp.async mapping: thread -> 4 A rows + 4 B rows, 16B each
    const int rowi = tid >> 3;
    const int cg   = tid & 7;
    uint32_t a_off[4];
#pragma unroll
    for (int i = 0; i < 4; ++i) {
        uint32_t o = (uint32_t)(rowi + 32 * i) * 128u + (uint32_t)cg * 16u;
        a_off[i] = o ^ ((o >> 3) & 0x70u);
    }
    const __half* rowA = g_Ah + (size_t)(bm + rowi) * KTOT + cg * 8;
    const __half* rowB = g_Bh + (size_t)(bn + rowi) * KTOT + cg * 8;

    // load chunk c into stage st; signal full[st] via cp.async arrive
    auto load_chunk = [&](int c, uint32_t st) {
        const uint32_t sb = sbase + st * STAGE_BYTES;
        const __half* pa = rowA + c * 64;
        const __half* pb = rowB + c * 64;
#pragma unroll
        for (int i = 0; i < 4; ++i)
            asm volatile("cp.async.cg.shared.global [%0], [%1], 16;"
                         :: "r"(sb + a_off[i]),
                            "l"(pa + (size_t)i * (32 * KTOT)) : "memory");
#pragma unroll
        for (int i = 0; i < 4; ++i)
            asm volatile("cp.async.cg.shared.global [%0], [%1], 16;"
                         :: "r"(sb + a_off[i] + 16384u),
                            "l"(pb + (size_t)i * (32 * KTOT)) : "memory");
        asm volatile("cp.async.mbarrier.arrive.noinc.shared.b64 [%0];"
                     :: "r"(mbF + st * 8) : "memory");
    };

    // ldmatrix per-lane offsets (stage-relative)
    uint32_t a_rel[2], a_msk[2];
#pragma unroll
    for (int mt = 0; mt < 2; ++mt) {
        uint32_t m = wm * 32 + mt * 16 + (lane & 15);
        a_rel[mt] = m * 128u;
        a_msk[mt] = ((m & 7u) << 4) ^ ((uint32_t)(lane >> 4) * 16u);
    }
    uint32_t b_rel[4], b_msk[4];
#pragma unroll
    for (int np = 0; np < 4; ++np) {
        uint32_t n = wn * 64 + np * 16 + ((uint32_t)((lane >> 4) & 1) * 8u) + (lane & 7);
        b_rel[np] = 16384u + n * 128u;
        b_msk[np] = ((n & 7u) << 4) ^ ((uint32_t)((lane >> 3) & 1) * 16u);
    }

    float acc[2][8][4];
#pragma unroll
    for (int mt = 0; mt < 2; ++mt)
#pragma unroll
        for (int nt = 0; nt < 8; ++nt)
#pragma unroll
            for (int j = 0; j < 4; ++j) acc[mt][nt][j] = 0.f;

    // prologue: fill all 3 stages (no empty-wait on first round)
    load_chunk(0, 0);
    load_chunk(1, 1);
    load_chunk(2, 2);

    uint32_t st  = 0;   // stage of chunk c
    uint32_t par = 0;   // parity = (c / NSTAGE) & 1, for both full & empty waits

#pragma unroll 1
    for (int c = 0; c < NCHUNK; ++c) {
        mbar_wait(mbF + st * 8, par);            // chunk c data ready

        const uint32_t stg = sbase + st * STAGE_BYTES;
#pragma unroll
        for (int ks = 0; ks < 4; ++ks) {
            const uint32_t kb = (uint32_t)ks * 32u;
            uint32_t a[2][4], bfr[4][4];
#pragma unroll
            for (int mt = 0; mt < 2; ++mt)
                ldsm_x4(a[mt][0], a[mt][1], a[mt][2], a[mt][3],
                        stg + a_rel[mt] + (kb ^ a_msk[mt]));
#pragma unroll
            for (int np = 0; np < 4; ++np)
                ldsm_x4(bfr[np][0], bfr[np][1], bfr[np][2], bfr[np][3],
                        stg + b_rel[np] + (kb ^ b_msk[np]));
#pragma unroll
            for (int mt = 0; mt < 2; ++mt)
#pragma unroll
                for (int np = 0; np < 4; ++np) {
                    mma16816(acc[mt][np * 2 + 0], a[mt], &bfr[np][0]);
                    mma16816(acc[mt][np * 2 + 1], a[mt], &bfr[np][2]);
                }
        }

        // done reading stage st for this round
        asm volatile("mbarrier.arrive.shared.b64 _, [%0];"
                     :: "r"(mbE + st * 8) : "memory");

        if (c + NSTAGE < NCHUNK) {
            // chunk c+3 reuses stage st; wait until ALL warps finished round c
            mbar_wait(mbE + st * 8, par);
            load_chunk(c + NSTAGE, st);
        }

        if (++st == NSTAGE) { st = 0; par ^= 1; }
    }

    // epilogue: direct float2 stores (per-warp data only; no smem reuse)
#pragma unroll
    for (int mt = 0; mt < 2; ++mt) {
        const int row0 = bm + wm * 32 + mt * 16 + (lane >> 2);
#pragma unroll
        for (int nt = 0; nt < 8; ++nt) {
            const int col = bn + wn * 64 + nt * 8 + (lane & 3) * 2;
            float* c0 = C + (size_t)row0 * NTOT + col;
            float* c1 = c0 + 8 * NTOT;
            *(float2*)c0 = make_float2(acc[mt][nt][0], acc[mt][nt][1]);
            *(float2*)c1 = make_float2(acc[mt][nt][2], acc[mt][nt][3]);
        }
    }
}

// ----------------------------- launcher -----------------------------------
extern "C" void kernel_launch(void* const* d_in, const int* in_sizes, int n_in,
                              void* d_out, int out_size) {
    const float* A = (const float*)d_in[0];   // [8, 8192, 512]
    const float* W = (const float*)d_in[1];   // [8, 1024, 512]
    float* C = (float*)d_out;                 // [8192, 1024]
    (void)in_sizes; (void)n_in; (void)out_size;

    const int smem_bytes = NSTAGE * STAGE_BYTES;   // 96 KB
    static bool attr_done = false;                 // host-side config only
    if (!attr_done) {
        cudaFuncSetAttribute(gemm_mma_f16,
                             cudaFuncAttributeMaxDynamicSharedMemorySize, smem_bytes);
        attr_done = true;
    }

    cast_kernel<<<MTOT + NTOT, 256>>>(A, W);       // 9216 blocks

    dim3 grid(NTOT / BNT, MTOT / BMT);             // (8, 64) = 512 CTAs
    gemm_mma_f16<<<grid, 256, smem_bytes>>>(C);
}

// round 9
// speedup vs baseline: 1.4091x; 1.4091x over previous
#include <cuda_runtime.h>
#include <cuda_fp16.h>
#include <cstdint>
#include <cstddef>

// ---------------------------------------------------------------------------
// GemmRS: out[g,n] = sum_{s,k} A[s,g,k] * W[s,n,k]  == GEMM M=8192,N=1024,K=4096
// fp16 cast both operands (validated rel_err 2.9e-4 < 1e-3 threshold).
// mma.sync.m16n8k16 f16 -> fp32. 3-stage cp.async pipeline:
//   full[st]: armed by cp.async.mbarrier.arrive.noinc (init 256, HW-async)
//   empty[st]: per-WARP arrives (init 8, lane-0 elected)  [R8 bug fix #1]
//   try_wait with suspend hint -> no smem-port spinning   [R8 bug fix #2]
// ---------------------------------------------------------------------------

#define MTOT 8192
#define NTOT 1024
#define KTOT 4096
#define NCHUNK 64              // KTOT / 64
#define BMT  128
#define BNT  128
#define STAGE_BYTES 32768      // A 16KB + B 16KB
#define NSTAGE 3

__device__ __half g_Ah[(size_t)MTOT * KTOT];
__device__ __half g_Bh[(size_t)NTOT * KTOT];

static __device__ __forceinline__ uint32_t smem_u32(const void* p) {
    uint32_t a;
    asm("{ .reg .u64 t; cvta.to.shared.u64 t, %1; cvt.u32.u64 %0, t; }"
        : "=r"(a) : "l"(p));
    return a;
}
static __device__ __forceinline__ void ldsm_x4(uint32_t& r0, uint32_t& r1,
                                               uint32_t& r2, uint32_t& r3,
                                               uint32_t addr) {
    asm volatile("ldmatrix.sync.aligned.m8n8.x4.shared.b16 {%0,%1,%2,%3}, [%4];"
                 : "=r"(r0), "=r"(r1), "=r"(r2), "=r"(r3) : "r"(addr));
}
static __device__ __forceinline__ void mma16816(float* c, const uint32_t* a,
                                                const uint32_t* b) {
    asm volatile(
        "mma.sync.aligned.m16n8k16.row.col.f32.f16.f16.f32 "
        "{%0,%1,%2,%3}, {%4,%5,%6,%7}, {%8,%9}, {%0,%1,%2,%3};"
        : "+f"(c[0]), "+f"(c[1]), "+f"(c[2]), "+f"(c[3])
        : "r"(a[0]), "r"(a[1]), "r"(a[2]), "r"(a[3]), "r"(b[0]), "r"(b[1]));
}
// try_wait with HW-sleep suspend hint (no smem spin)
static __device__ __forceinline__ void mbar_wait(uint32_t addr, uint32_t parity) {
    asm volatile(
        "{ .reg .pred P;\n\t"
        "WAIT_%=:\n\t"
        "mbarrier.try_wait.parity.shared.b64 P, [%0], %1, 0x989680;\n\t"
        "@P bra.uni DONE_%=;\n\t"
        "bra.uni WAIT_%=;\n\t"
        "DONE_%=:\n\t}"
        :: "r"(addr), "r"(parity) : "memory");
}

// ------------------------- fused cast prepass ------------------------------
__global__ __launch_bounds__(256) void cast_kernel(const float* __restrict__ A,
                                                   const float* __restrict__ W) {
    const int b = blockIdx.x;
    const int t = threadIdx.x;
    const int k0 = t << 4;
    const int s  = k0 >> 9;
    const int kl = k0 & 511;

    const bool isA = (b < MTOT);
    const int  row = isA ? b : (b - MTOT);
    const float4* src = isA ? (const float4*)(A + ((size_t)s * MTOT + row) * 512 + kl)
                            : (const float4*)(W + ((size_t)s * NTOT + row) * 512 + kl);
    float4 v0 = src[0], v1 = src[1], v2 = src[2], v3 = src[3];
    float x[16] = {v0.x,v0.y,v0.z,v0.w, v1.x,v1.y,v1.z,v1.w,
                   v2.x,v2.y,v2.z,v2.w, v3.x,v3.y,v3.z,v3.w};
    uint32_t h[8];
#pragma unroll
    for (int p = 0; p < 8; ++p) {
        __half h0 = __float2half_rn(x[2*p]);
        __half h1 = __float2half_rn(x[2*p+1]);
        h[p] = (uint32_t)__half_as_ushort(h0) |
               ((uint32_t)__half_as_ushort(h1) << 16);
    }
    uint4* dst = (uint4*)((isA ? g_Ah : g_Bh) + (size_t)row * KTOT + k0);
    dst[0] = make_uint4(h[0], h[1], h[2], h[3]);
    dst[1] = make_uint4(h[4], h[5], h[6], h[7]);
}

// ----------------------------- main GEMM ----------------------------------
// CTA 128x128, 8 warps 4(M)x2(N), warp tile 32x64, BK=64, 3-stage pipeline,
// occupancy 2. SW128-swizzled smem tiles. Decoupled mbarrier pipeline.
__global__ __launch_bounds__(256, 2)
void gemm_mma_f16(float* __restrict__ C) {
    extern __shared__ char dsm[];
    __shared__ __align__(16) unsigned long long mb_full[NSTAGE];
    __shared__ __align__(16) unsigned long long mb_empty[NSTAGE];

    const uint32_t sbase = smem_u32(dsm);
    const uint32_t mbF = smem_u32(&mb_full[0]);
    const uint32_t mbE = smem_u32(&mb_empty[0]);

    const int tid  = threadIdx.x;
    const int wid  = tid >> 5;
    const int lane = tid & 31;
    const int wm   = wid & 3;
    const int wn   = wid >> 2;
    const int bm   = blockIdx.y * BMT;
    const int bn   = blockIdx.x * BNT;

    if (tid == 0) {
#pragma unroll
        for (int s = 0; s < NSTAGE; ++s) {
            asm volatile("mbarrier.init.shared.b64 [%0], %1;"
                         :: "r"(mbF + s * 8), "r"(256) : "memory");   // async arrives
            asm volatile("mbarrier.init.shared.b64 [%0], %1;"
                         :: "r"(mbE + s * 8), "r"(8) : "memory");     // warp arrives
        }
    }
    __syncthreads();

    // cp.async mapping: thread -> 4 A rows + 4 B rows, 16B each
    const int rowi = tid >> 3;
    const int cg   = tid & 7;
    uint32_t a_off[4];
#pragma unroll
    for (int i = 0; i < 4; ++i) {
        uint32_t o = (uint32_t)(rowi + 32 * i) * 128u + (uint32_t)cg * 16u;
        a_off[i] = o ^ ((o >> 3) & 0x70u);
    }
    const __half* rowA = g_Ah + (size_t)(bm + rowi) * KTOT + cg * 8;
    const __half* rowB = g_Bh + (size_t)(bn + rowi) * KTOT + cg * 8;

    // load chunk c into stage st; full[st] armed when this thread's asyncs land
    auto load_chunk = [&](int c, uint32_t st) {
        const uint32_t sb = sbase + st * STAGE_BYTES;
        const __half* pa = rowA + c * 64;
        const __half* pb = rowB + c * 64;
#pragma unroll
        for (int i = 0; i < 4; ++i)
            asm volatile("cp.async.cg.shared.global [%0], [%1], 16;"
                         :: "r"(sb + a_off[i]),
                            "l"(pa + (size_t)i * (32 * KTOT)) : "memory");
#pragma unroll
        for (int i = 0; i < 4; ++i)
            asm volatile("cp.async.cg.shared.global [%0], [%1], 16;"
                         :: "r"(sb + a_off[i] + 16384u),
                            "l"(pb + (size_t)i * (32 * KTOT)) : "memory");
        asm volatile("cp.async.mbarrier.arrive.noinc.shared.b64 [%0];"
                     :: "r"(mbF + st * 8) : "memory");
    };

    // ldmatrix per-lane offsets (stage-relative)
    uint32_t a_rel[2], a_msk[2];
#pragma unroll
    for (int mt = 0; mt < 2; ++mt) {
        uint32_t m = wm * 32 + mt * 16 + (lane & 15);
        a_rel[mt] = m * 128u;
        a_msk[mt] = ((m & 7u) << 4) ^ ((uint32_t)(lane >> 4) * 16u);
    }
    uint32_t b_rel[4], b_msk[4];
#pragma unroll
    for (int np = 0; np < 4; ++np) {
        uint32_t n = wn * 64 + np * 16 + ((uint32_t)((lane >> 4) & 1) * 8u) + (lane & 7);
        b_rel[np] = 16384u + n * 128u;
        b_msk[np] = ((n & 7u) << 4) ^ ((uint32_t)((lane >> 3) & 1) * 16u);
    }

    float acc[2][8][4];
#pragma unroll
    for (int mt = 0; mt < 2; ++mt)
#pragma unroll
        for (int nt = 0; nt < 8; ++nt)
#pragma unroll
            for (int j = 0; j < 4; ++j) acc[mt][nt][j] = 0.f;

    // prologue: fill all 3 stages (stages start empty; no wait)
    load_chunk(0, 0);
    load_chunk(1, 1);
    load_chunk(2, 2);

    uint32_t st   = 0;   // stage of chunk c
    uint32_t parF = 0;   // round parity: flips when st wraps

#pragma unroll 1
    for (int c = 0; c < NCHUNK; ++c) {
        mbar_wait(mbF + st * 8, parF);           // chunk c data visible

        const uint32_t stg = sbase + st * STAGE_BYTES;
#pragma unroll
        for (int ks = 0; ks < 4; ++ks) {
            const uint32_t kb = (uint32_t)ks * 32u;
            uint32_t a[2][4], bfr[4][4];
#pragma unroll
            for (int mt = 0; mt < 2; ++mt)
                ldsm_x4(a[mt][0], a[mt][1], a[mt][2], a[mt][3],
                        stg + a_rel[mt] + (kb ^ a_msk[mt]));
#pragma unroll
            for (int np = 0; np < 4; ++np)
                ldsm_x4(bfr[np][0], bfr[np][1], bfr[np][2], bfr[np][3],
                        stg + b_rel[np] + (kb ^ b_msk[np]));
#pragma unroll
            for (int mt = 0; mt < 2; ++mt)
#pragma unroll
                for (int np = 0; np < 4; ++np) {
                    mma16816(acc[mt][np * 2 + 0], a[mt], &bfr[np][0]);
                    mma16816(acc[mt][np * 2 + 1], a[mt], &bfr[np][2]);
                }
        }

        // this warp is done reading stage st this round (1 arrive per warp)
        if (lane == 0)
            asm volatile("mbarrier.arrive.shared.b64 _, [%0];"
                         :: "r"(mbE + st * 8) : "memory");

        if (c + NSTAGE < NCHUNK) {
            // reuse stage st for chunk c+3 once ALL warps finished round c
            mbar_wait(mbE + st * 8, parF);
            load_chunk(c + NSTAGE, st);
        }

        if (++st == NSTAGE) { st = 0; parF ^= 1; }
    }

    // epilogue: direct float2 stores (register data only)
#pragma unroll
    for (int mt = 0; mt < 2; ++mt) {
        const int row0 = bm + wm * 32 + mt * 16 + (lane >> 2);
#pragma unroll
        for (int nt = 0; nt < 8; ++nt) {
            const int col = bn + wn * 64 + nt * 8 + (lane & 3) * 2;
            float* c0 = C + (size_t)row0 * NTOT + col;
            float* c1 = c0 + 8 * NTOT;
            *(float2*)c0 = make_float2(acc[mt][nt][0], acc[mt][nt][1]);
            *(float2*)c1 = make_float2(acc[mt][nt][2], acc[mt][nt][3]);
        }
    }
}

// ----------------------------- launcher -----------------------------------
extern "C" void kernel_launch(void* const* d_in, const int* in_sizes, int n_in,
                              void* d_out, int out_size) {
    const float* A = (const float*)d_in[0];   // [8, 8192, 512]
    const float* W = (const float*)d_in[1];   // [8, 1024, 512]
    float* C = (float*)d_out;                 // [8192, 1024]
    (void)in_sizes; (void)n_in; (void)out_size;

    const int smem_bytes = NSTAGE * STAGE_BYTES;   // 96 KB
    static bool attr_done = false;                 // host-side config only
    if (!attr_done) {
        cudaFuncSetAttribute(gemm_mma_f16,
                             cudaFuncAttributeMaxDynamicSharedMemorySize, smem_bytes);
        attr_done = true;
    }

    cast_kernel<<<MTOT + NTOT, 256>>>(A, W);       // 9216 blocks

    dim3 grid(NTOT / BNT, MTOT / BMT);             // (8, 64) = 512 CTAs
    gemm_mma_f16<<<grid, 256, smem_bytes>>>(C);
}